// round 16
// baseline (speedup 1.0000x reference)
#include <cuda_runtime.h>
#include <cuda_fp16.h>
#include <cstdint>

#define SLOPE 0.01f
#define BN_EPS 1e-5f

#define MAX_NIN   80000
#define MAX_NOUT  200000
#define MAX_BLK   1600

// Scratch (static device globals — no allocation allowed)
__device__ float    g_h [MAX_NIN  * 64];
__device__ float    g_t1[MAX_NOUT * 64];
__device__ float    g_t2[MAX_NOUT * 64];
__device__ float    g_t3[MAX_NOUT * 64];
__device__ float    g_part[MAX_BLK * 128];
__device__ float    g_ab[4 * 128];              // per BN stage: a[64], b[64]
__device__ uint32_t g_Bimg[252 * 2048];         // ALL 5 convs' fp16 hi/lo weight images
__device__ uint32_t g_s0[MAX_NOUT * 64];        // fp16 feature buffers (ping)
__device__ uint32_t g_s1[MAX_NOUT * 64];        // (pong)

// Chunk-base offsets into g_Bimg per conv (in 2048-u32 chunks)
#define BOFF_T  0       // trans: 108 chunks
#define BOFF_U  108     // up:     54 chunks
#define BOFF_1  162     // conv1:  18 chunks
#define BOFF_2  180     // conv2:  18 chunks
#define BOFF_3  198     // conv3:  54 chunks

// ---------------------------------------------------------------------------
// helpers
// ---------------------------------------------------------------------------
__device__ __forceinline__ uint32_t packh(float a, float b) {
    __half2 t = __floats2half2_rn(a, b);        // .x in low 16 bits
    return *reinterpret_cast<uint32_t*>(&t);
}
__device__ __forceinline__ uint32_t smem_u32(const void* p) {
    uint32_t a;
    asm("{ .reg .u64 t; cvta.to.shared.u64 t, %1; cvt.u32.u64 %0, t; }" : "=r"(a) : "l"(p));
    return a;
}

// m16n8k16 fp16 MMA, fp32 accumulate
__device__ __forceinline__ void mma_f16(float* c, const uint32_t* a, const uint32_t* b) {
    asm volatile(
        "mma.sync.aligned.m16n8k16.row.col.f32.f16.f16.f32 "
        "{%0,%1,%2,%3}, {%4,%5,%6,%7}, {%8,%9}, {%0,%1,%2,%3};"
        : "+f"(c[0]), "+f"(c[1]), "+f"(c[2]), "+f"(c[3])
        : "r"(a[0]), "r"(a[1]), "r"(a[2]), "r"(a[3]), "r"(b[0]), "r"(b[1]));
}

#define LDSM4(R0, R1, R2, R3, addr) \
    asm volatile("ldmatrix.sync.aligned.m8n8.x4.shared.b16 {%0,%1,%2,%3}, [%4];" \
                 : "=r"(R0), "=r"(R1), "=r"(R2), "=r"(R3) : "r"(addr))

#define CP16(dst, src, sz) \
    asm volatile("cp.async.cg.shared.global [%0], [%1], 16, %2;" \
                 :: "r"(dst), "l"(src), "r"(sz) : "memory")
#define CP_COMMIT() asm volatile("cp.async.commit_group;" ::: "memory")

// Named group barrier: group 0 -> bar 1, group 1 -> bar 2 (128 threads each)
#define GBAR(grp) asm volatile("bar.sync %0, 128;" :: "r"((grp) + 1) : "memory")

// B tile swizzle: [64 x 32] u32, conflict-free (proven R6-R15)
__device__ __forceinline__ int sidxB(int row, int col) {
    return row * 32 + (col ^ ((row & 7) * 4));
}
// A tile swizzle: [rows x 16] u32, conflict-free for LDSM (proven R11-R15)
__device__ __forceinline__ int sidxA(int row, int col) {
    return row * 16 + (col ^ (((row >> 1) & 3) * 4));
}

// SMEM (u32 units), per group: A 2x1024 (64x16), B 2x2048 (64x32).
// grp0 A @0, grp1 A @2048, grp0 B @4096, grp1 B @8192. Total 12288 u32.
#define SMEM_BYTES (12288 * 4)                  // 48 KB -> 4 CTAs/SM

// ---------------------------------------------------------------------------
// Weight pre-transform: per chunk (32-wide Cin slice of one tap) build a
// 64x32 u32 tile: cols 0-15 = fp16 hi plane, 16-31 = fp16 lo plane, swizzled.
// ---------------------------------------------------------------------------
__global__ void transpose_W(const float* __restrict__ W, uint32_t* __restrict__ Bimg,
                            int total)
{
    const int e = blockIdx.x * 256 + threadIdx.x;
    if (e >= total) return;
    const int chunk = e >> 10;
    const int kp    = (e >> 6) & 15;
    const int n     = e & 63;
    const int kbase = chunk * 32 + kp * 2;
    const float w0 = W[(size_t)kbase * 64 + n];
    const float w1 = W[(size_t)(kbase + 1) * 64 + n];
    const float h0 = __half2float(__float2half_rn(w0));
    const float h1 = __half2float(__float2half_rn(w1));
    uint32_t* dst = Bimg + (size_t)chunk * 2048;
    dst[sidxB(n, kp)]      = packh(w0, w1);
    dst[sidxB(n, 16 + kp)] = packh(w0 - h0, w1 - h1);
}

// ---------------------------------------------------------------------------
// Feature pre-convert: fp32 [N, C] (+ optional BN affine) -> packed fp16.
// ---------------------------------------------------------------------------
__global__ __launch_bounds__(256)
void split_feats(const float* __restrict__ in, const float* __restrict__ ab,
                 uint32_t* __restrict__ outp, int N, int C)
{
    const int i = blockIdx.x * 256 + threadIdx.x;
    if (i >= N * (C / 4)) return;
    const int p = i / (C / 4);
    const int q = i - p * (C / 4);
    float4 v = ((const float4*)in)[i];
    if (ab) {
        const int ch = q * 4;
        v.x = v.x * ab[ch + 0] + ab[64 + ch + 0];
        v.y = v.y * ab[ch + 1] + ab[64 + ch + 1];
        v.z = v.z * ab[ch + 2] + ab[64 + ch + 2];
        v.w = v.w * ab[ch + 3] + ab[64 + ch + 3];
    }
    uint32_t* base = outp + (size_t)p * (C / 2);
    *(uint2*)&base[q * 2] = make_uint2(packh(v.x, v.y), packh(v.z, v.w));
}

// ---------------------------------------------------------------------------
// fp16 asymmetric-split gather-GEMM conv (2 MMA terms: A*Bh + A*Bl).
// Tile: 128 output points x 64 Cout, TWO independent 4-warp pipelines with
// own buffers + named barriers. Depth-2 rings (48 KB SMEM) + forced
// 4 CTAs/SM via __launch_bounds__(256,4): 32 warps/SM, 8 pipelines/SM.
// issue(c+1) overlaps compute(c); register-lean per-p B fragment loads.
// MODE 0: out = lrelu(acc), fp32 store + per-block BN stats partials
// MODE 1: u = acc + skip, stored directly as packed fp16
// ---------------------------------------------------------------------------
template<int KK, int CIN, int MODE>
__global__ __launch_bounds__(256, 4)
void conv_mma(const uint32_t* __restrict__ feats,   // fp16 features [N, CIN/2] u32
              const uint32_t* __restrict__ Bimg,
              const int*   __restrict__ nbr,
              const float* __restrict__ skip,
              float*       __restrict__ out,
              uint32_t*    __restrict__ sout,
              float*       __restrict__ partials,
              int Nsrc, int Nout)
{
    constexpr int NSUB = CIN / 32;
    constexpr int NCH  = KK * NSUB;

    extern __shared__ uint32_t smu[];
    const uint32_t sb = smem_u32(smu);

    const int tid    = threadIdx.x;
    const int lane   = tid & 31;
    const int grp    = tid >> 7;            // pipeline group 0/1
    const int wg_tid = tid & 127;
    const int wwid   = (tid >> 5) & 3;      // warp within group
    const int g      = lane >> 2, t4 = lane & 3;
    const int wm     = wwid & 1,  wn = wwid >> 1;   // 2x2 warp grid per group
    const int n0     = blockIdx.x * 128;
    const int rbase  = grp * 64;            // group's row base within tile

    // SMEM bases (u32 units) for this group (depth-2 rings)
    const int A0 = grp * 2048;              // 2 bufs x 1024
    const int B0 = 4096 + grp * 4096;       // 2 bufs x 2048

    float acc[2][4][4];
    #pragma unroll
    for (int mm = 0; mm < 2; ++mm)
        #pragma unroll
        for (int nn = 0; nn < 4; ++nn)
            #pragma unroll
            for (int q = 0; q < 4; ++q) acc[mm][nn][q] = 0.f;

    // Gather mapping: each thread owns 2 rows of its group's 64-row tile
    const int sub  = wg_tid & 3;            // 16B piece within 64B row-slice
    const int row0 = wg_tid >> 2;           // 0..31; rows row0, row0+32
    const int soffb = sub * 4;
    int cidx0 = Nsrc, cidx1 = Nsrc;

    auto issue = [&](int c, int buf) {
        const int k = c / NSUB, s = c - k * NSUB;
        const uint32_t Ab = sb + (A0 + buf * 1024) * 4;
        const uint32_t Bb = sb + (B0 + buf * 2048) * 4;
        if (s == 0) {                       // refresh idx cache once per tap
            const int g0 = n0 + rbase + row0, g1 = n0 + rbase + row0 + 32;
            cidx0 = (g0 < Nout) ? nbr[(size_t)k * Nout + g0] : Nsrc;
            cidx1 = (g1 < Nout) ? nbr[(size_t)k * Nout + g1] : Nsrc;
        }
        {
            const bool v0 = (unsigned)cidx0 < (unsigned)Nsrc;
            const uint32_t* sp = feats + (size_t)(v0 ? cidx0 : 0) * (CIN / 2) + s * 16 + soffb;
            CP16(Ab + sidxA(row0, soffb) * 4, sp, v0 ? 16 : 0);
        }
        {
            const bool v1 = (unsigned)cidx1 < (unsigned)Nsrc;
            const uint32_t* sp = feats + (size_t)(v1 ? cidx1 : 0) * (CIN / 2) + s * 16 + soffb;
            CP16(Ab + sidxA(row0 + 32, soffb) * 4, sp, v1 ? 16 : 0);
        }
        const uint32_t* bs = Bimg + (size_t)c * 2048;
        #pragma unroll
        for (int j = 0; j < 4; ++j)
            CP16(Bb + (wg_tid + j * 128) * 16, bs + (wg_tid + j * 128) * 4, 16);
        CP_COMMIT();
    };

    auto compute = [&](int buf) {
        const uint32_t Ab = sb + (A0 + buf * 1024) * 4;
        const uint32_t Bb = sb + (B0 + buf * 2048) * 4;
        #pragma unroll
        for (int ks = 0; ks < 2; ++ks) {
            uint32_t ah[2][4];
            #pragma unroll
            for (int mm = 0; mm < 2; ++mm) {
                const int arow = wm * 32 + mm * 16 + (lane & 15);
                const int acol = ks * 8 + (lane >> 4) * 4;
                LDSM4(ah[mm][0], ah[mm][1], ah[mm][2], ah[mm][3],
                      Ab + sidxA(arow, acol) * 4);
            }
            #pragma unroll
            for (int p = 0; p < 2; ++p) {               // register-lean: B per p
                uint32_t bh[4], bl[4];
                const int brow = wn * 32 + p * 16 + ((lane >> 4) & 1) * 8 + (lane & 7);
                const int bcol = ks * 8 + ((lane >> 3) & 1) * 4;
                LDSM4(bh[0], bh[1], bh[2], bh[3], Bb + sidxB(brow, bcol) * 4);
                LDSM4(bl[0], bl[1], bl[2], bl[3], Bb + sidxB(brow, bcol + 16) * 4);
                #pragma unroll
                for (int mm = 0; mm < 2; ++mm)
                    #pragma unroll
                    for (int nq = 0; nq < 2; ++nq) {
                        const int nn = p * 2 + nq;
                        mma_f16(acc[mm][nn], ah[mm], &bh[nq * 2]);
                        mma_f16(acc[mm][nn], ah[mm], &bl[nq * 2]);
                    }
            }
        }
    };

    issue(0, 0);
    #pragma unroll 1
    for (int c = 0; c < NCH; ++c) {
        asm volatile("cp.async.wait_group 0;" ::: "memory");
        GBAR(grp);                             // group-local barrier only
        if (c + 1 < NCH) issue(c + 1, (c + 1) & 1);
        compute(c & 1);
    }

    if (MODE == 1) {
        // --- epilogue: u = acc + skip, write packed fp16 directly ---
        #pragma unroll
        for (int mm = 0; mm < 2; ++mm)
            #pragma unroll
            for (int half = 0; half < 2; ++half) {
                const int r = n0 + rbase + wm * 32 + mm * 16 + g + half * 8;
                if (r < Nout) {
                    uint32_t* base = sout + (size_t)r * 32;
                    #pragma unroll
                    for (int nn = 0; nn < 4; ++nn) {
                        const int col = wn * 32 + nn * 8 + t4 * 2;
                        const float2 s2 = *(const float2*)&skip[(size_t)r * 64 + col];
                        const float v0 = acc[mm][nn][half * 2 + 0] + s2.x;
                        const float v1 = acc[mm][nn][half * 2 + 1] + s2.y;
                        base[col / 2] = packh(v0, v1);
                    }
                }
            }
    } else {
        // --- epilogue: lrelu, fp32 store, per-block BN stats partials ---
        float sl[8], ql[8];
        #pragma unroll
        for (int j = 0; j < 8; ++j) { sl[j] = 0.f; ql[j] = 0.f; }
        #pragma unroll
        for (int mm = 0; mm < 2; ++mm)
            #pragma unroll
            for (int half = 0; half < 2; ++half) {
                const int r = n0 + rbase + wm * 32 + mm * 16 + g + half * 8;
                if (r < Nout) {
                    #pragma unroll
                    for (int nn = 0; nn < 4; ++nn) {
                        float v0 = acc[mm][nn][half * 2 + 0];
                        float v1 = acc[mm][nn][half * 2 + 1];
                        v0 = v0 >= 0.f ? v0 : SLOPE * v0;
                        v1 = v1 >= 0.f ? v1 : SLOPE * v1;
                        const int col = wn * 32 + nn * 8 + t4 * 2;
                        *(float2*)&out[(size_t)r * 64 + col] = make_float2(v0, v1);
                        sl[nn * 2 + 0] += v0; ql[nn * 2 + 0] += v0 * v0;
                        sl[nn * 2 + 1] += v1; ql[nn * 2 + 1] += v1 * v1;
                    }
                }
            }
        __syncthreads();                 // both groups done; reuse conv SMEM
        float* red = (float*)smu;        // [2][64][32]
        const int ctr = (grp * 2 + wm) * 8 + g;     // 0..31 per column
        #pragma unroll
        for (int nn = 0; nn < 4; ++nn)
            #pragma unroll
            for (int b = 0; b < 2; ++b) {
                const int col = wn * 32 + nn * 8 + t4 * 2 + b;
                red[col * 32 + ctr]        = sl[nn * 2 + b];
                red[2048 + col * 32 + ctr] = ql[nn * 2 + b];
            }
        __syncthreads();
        if (tid < 128) {
            const int col = tid & 63, stat = tid >> 6;
            const float* src = red + stat * 2048 + col * 32;
            float s = 0.f;
            #pragma unroll
            for (int j = 0; j < 32; ++j) s += src[j];
            partials[blockIdx.x * 128 + stat * 64 + col] = s;
        }
    }
}

// ---------------------------------------------------------------------------
// Parallel finalize: grid = 64 blocks (one per channel), 256 threads.
// Fixed-order tree reduction -> deterministic.
// ---------------------------------------------------------------------------
__global__ __launch_bounds__(256)
void finalize_stats(const float* __restrict__ partial, int nblk, float invN,
                    const float* __restrict__ gamma, const float* __restrict__ beta,
                    float* __restrict__ ab)
{
    __shared__ double sh[256];
    const int ch   = blockIdx.x;
    const int t    = threadIdx.x;
    const int half = t >> 7;           // 0: S, 1: SS
    const int tt   = t & 127;
    double s = 0.0;
    for (int b = tt; b < nblk; b += 128)
        s += (double)partial[b * 128 + half * 64 + ch];
    sh[t] = s;
    __syncthreads();
    #pragma unroll
    for (int off = 64; off >= 1; off >>= 1) {
        if (tt < off) sh[t] += sh[t + off];
        __syncthreads();
    }
    if (t == 0) {
        const double S  = sh[0];
        const double SS = sh[128];
        const float m   = (float)(S * (double)invN);
        const float var = (float)(SS * (double)invN) - m * m;
        const float inv = rsqrtf(var + BN_EPS);
        const float a   = gamma[ch] * inv;
        ab[ch]      = a;
        ab[64 + ch] = beta[ch] - m * a;
    }
}

__global__ __launch_bounds__(256)
void apply_affine(const float* __restrict__ t, const float* __restrict__ ab,
                  float* __restrict__ out, int total4)
{
    const int i = blockIdx.x * blockDim.x + threadIdx.x;
    if (i >= total4) return;
    float4 v = ((const float4*)t)[i];
    const int c = (i & 15) * 4;
    v.x = v.x * ab[c + 0] + ab[64 + c + 0];
    v.y = v.y * ab[c + 1] + ab[64 + c + 1];
    v.z = v.z * ab[c + 2] + ab[64 + c + 2];
    v.w = v.w * ab[c + 3] + ab[64 + c + 3];
    ((float4*)out)[i] = v;
}

// ---------------------------------------------------------------------------
extern "C" void kernel_launch(void* const* d_in, const int* in_sizes, int n_in,
                              void* d_out, int out_size)
{
    const float* x      = (const float*)d_in[0];
    const float* skip   = (const float*)d_in[1];
    const int*   nbr_t  = (const int*)d_in[2];
    const int*   nbr_up = (const int*)d_in[3];
    const int*   nbr1   = (const int*)d_in[4];
    const int*   nbr2   = (const int*)d_in[5];
    const int*   nbr3   = (const int*)d_in[6];
    const float* Wt     = (const float*)d_in[7];
    const float* Wu     = (const float*)d_in[8];
    const float* W1     = (const float*)d_in[9];
    const float* W2     = (const float*)d_in[10];
    const float* W3     = (const float*)d_in[11];
    const float* gt = (const float*)d_in[12]; const float* bt = (const float*)d_in[13];
    const float* g1 = (const float*)d_in[14]; const float* b1 = (const float*)d_in[15];
    const float* g2 = (const float*)d_in[16]; const float* b2 = (const float*)d_in[17];
    const float* g3 = (const float*)d_in[18]; const float* b3 = (const float*)d_in[19];

    const int N_in  = in_sizes[0] / 128;   // 80000
    const int N_out = in_sizes[1] / 64;    // 200000
    float* out = (float*)d_out;

    float *h_, *t1_, *t2_, *t3_, *part_, *ab_;
    uint32_t *bimg_, *s0_, *s1_;
    cudaGetSymbolAddress((void**)&h_,    g_h);
    cudaGetSymbolAddress((void**)&t1_,   g_t1);
    cudaGetSymbolAddress((void**)&t2_,   g_t2);
    cudaGetSymbolAddress((void**)&t3_,   g_t3);
    cudaGetSymbolAddress((void**)&part_, g_part);
    cudaGetSymbolAddress((void**)&ab_,   g_ab);
    cudaGetSymbolAddress((void**)&bimg_, g_Bimg);
    cudaGetSymbolAddress((void**)&s0_,   g_s0);
    cudaGetSymbolAddress((void**)&s1_,   g_s1);

    cudaFuncSetAttribute(conv_mma<27, 128, 0>, cudaFuncAttributeMaxDynamicSharedMemorySize, SMEM_BYTES);
    cudaFuncSetAttribute(conv_mma<27,  64, 1>, cudaFuncAttributeMaxDynamicSharedMemorySize, SMEM_BYTES);
    cudaFuncSetAttribute(conv_mma< 9,  64, 0>, cudaFuncAttributeMaxDynamicSharedMemorySize, SMEM_BYTES);
    cudaFuncSetAttribute(conv_mma<27,  64, 0>, cudaFuncAttributeMaxDynamicSharedMemorySize, SMEM_BYTES);

    const int gin  = (N_in  + 127) / 128;   // 625
    const int gout = (N_out + 127) / 128;   // 1563

    // [0] convert x -> fp16 s0
    split_feats<<<(N_in * 32 + 255) / 256, 256>>>(x, nullptr, s0_, N_in, 128);
    // [1][2] weight transposes needed before the first conv
    transpose_W<<<(108 * 1024 + 255) / 256, 256>>>(Wt, bimg_ + BOFF_T * 2048, 108 * 1024);
    transpose_W<<<( 54 * 1024 + 255) / 256, 256>>>(Wu, bimg_ + BOFF_U * 2048,  54 * 1024);
    // [3] trans conv (the slot ncu samples) + lrelu -> h + stats
    conv_mma<27, 128, 0><<<gin, 256, SMEM_BYTES>>>(s0_, bimg_ + BOFF_T * 2048, nbr_t, nullptr, h_, nullptr, part_, N_in, N_in);
    // remaining weight transposes (off critical path)
    transpose_W<<<( 18 * 1024 + 255) / 256, 256>>>(W1, bimg_ + BOFF_1 * 2048,  18 * 1024);
    transpose_W<<<( 18 * 1024 + 255) / 256, 256>>>(W2, bimg_ + BOFF_2 * 2048,  18 * 1024);
    transpose_W<<<( 54 * 1024 + 255) / 256, 256>>>(W3, bimg_ + BOFF_3 * 2048,  54 * 1024);
    // finalize ab0 ; convert h
    finalize_stats<<<64, 256>>>(part_, gin, 1.0f / N_in, gt, bt, ab_ + 0);
    split_feats<<<(N_in * 16 + 255) / 256, 256>>>(h_, ab_ + 0, s1_, N_in, 64);

    // inverse conv + skip -> fp16 u directly into s0
    conv_mma<27, 64, 1><<<gout, 256, SMEM_BYTES>>>(s1_, bimg_ + BOFF_U * 2048, nbr_up, skip, nullptr, s0_, nullptr, N_in, N_out);

    // conv1 + lrelu -> t1 + stats ; finalize ab1 ; convert
    conv_mma<9, 64, 0><<<gout, 256, SMEM_BYTES>>>(s0_, bimg_ + BOFF_1 * 2048, nbr1, nullptr, t1_, nullptr, part_, N_out, N_out);
    finalize_stats<<<64, 256>>>(part_, gout, 1.0f / N_out, g1, b1, ab_ + 128);
    split_feats<<<(N_out * 16 + 255) / 256, 256>>>(t1_, ab_ + 128, s1_, N_out, 64);

    // conv2 + lrelu -> t2 + stats ; finalize ab2 ; convert
    conv_mma<9, 64, 0><<<gout, 256, SMEM_BYTES>>>(s1_, bimg_ + BOFF_2 * 2048, nbr2, nullptr, t2_, nullptr, part_, N_out, N_out);
    finalize_stats<<<64, 256>>>(part_, gout, 1.0f / N_out, g2, b2, ab_ + 256);
    split_feats<<<(N_out * 16 + 255) / 256, 256>>>(t2_, ab_ + 256, s0_, N_out, 64);

    // conv3 + lrelu -> t3 + stats ; finalize ab3
    conv_mma<27, 64, 0><<<gout, 256, SMEM_BYTES>>>(s0_, bimg_ + BOFF_3 * 2048, nbr3, nullptr, t3_, nullptr, part_, N_out, N_out);
    finalize_stats<<<64, 256>>>(part_, gout, 1.0f / N_out, g3, b3, ab_ + 384);

    // final BN3 apply -> d_out
    const int total4 = N_out * 16;
    apply_affine<<<(total4 + 255) / 256, 256>>>(t3_, ab_ + 384, out, total4);
}

// round 17
// speedup vs baseline: 1.0878x; 1.0878x over previous
#include <cuda_runtime.h>
#include <cuda_fp16.h>
#include <cstdint>

#define SLOPE 0.01f
#define BN_EPS 1e-5f

#define MAX_NIN   80000
#define MAX_NOUT  200000
#define MAX_BLK   1600

// Scratch (static device globals — no allocation allowed)
__device__ float    g_t3[MAX_NOUT * 64];
__device__ float    g_part[MAX_BLK * 128];
__device__ float    g_h [MAX_NIN  * 64];
__device__ float    g_t1[MAX_NOUT * 64];
__device__ float    g_t2[MAX_NOUT * 64];
__device__ float    g_ab[4 * 128];              // per BN stage: a[64], b[64]
__device__ uint32_t g_Bimg[252 * 2048];         // all convs' weight images
__device__ uint32_t g_s0[MAX_NOUT * 64];        // fp16 feature buffers (ping)
__device__ uint32_t g_s1[MAX_NOUT * 64];        // (pong)

// Chunk-base offsets into g_Bimg per conv (in u32; 2-term chunks are 2048 u32,
// 1-term (hi-only) chunks are 1024 u32)
#define BOFF_T  0                // trans: 108 chunks x 2048
#define BOFF_U  (108 * 2048)     // up:     54 chunks x 1024 (hi-only)
#define BOFF_1  (BOFF_U + 54 * 1024)   // conv1: 18 x 2048
#define BOFF_2  (BOFF_1 + 18 * 2048)   // conv2: 18 x 2048
#define BOFF_3  (BOFF_2 + 18 * 2048)   // conv3: 54 x 2048

// ---------------------------------------------------------------------------
// helpers
// ---------------------------------------------------------------------------
__device__ __forceinline__ uint32_t packh(float a, float b) {
    __half2 t = __floats2half2_rn(a, b);        // .x in low 16 bits
    return *reinterpret_cast<uint32_t*>(&t);
}
__device__ __forceinline__ uint32_t smem_u32(const void* p) {
    uint32_t a;
    asm("{ .reg .u64 t; cvta.to.shared.u64 t, %1; cvt.u32.u64 %0, t; }" : "=r"(a) : "l"(p));
    return a;
}

// m16n8k16 fp16 MMA, fp32 accumulate
__device__ __forceinline__ void mma_f16(float* c, const uint32_t* a, const uint32_t* b) {
    asm volatile(
        "mma.sync.aligned.m16n8k16.row.col.f32.f16.f16.f32 "
        "{%0,%1,%2,%3}, {%4,%5,%6,%7}, {%8,%9}, {%0,%1,%2,%3};"
        : "+f"(c[0]), "+f"(c[1]), "+f"(c[2]), "+f"(c[3])
        : "r"(a[0]), "r"(a[1]), "r"(a[2]), "r"(a[3]), "r"(b[0]), "r"(b[1]));
}

#define LDSM4(R0, R1, R2, R3, addr) \
    asm volatile("ldmatrix.sync.aligned.m8n8.x4.shared.b16 {%0,%1,%2,%3}, [%4];" \
                 : "=r"(R0), "=r"(R1), "=r"(R2), "=r"(R3) : "r"(addr))

#define CP16(dst, src, sz) \
    asm volatile("cp.async.cg.shared.global [%0], [%1], 16, %2;" \
                 :: "r"(dst), "l"(src), "r"(sz) : "memory")
#define CP_COMMIT() asm volatile("cp.async.commit_group;" ::: "memory")

// Named group barrier: group 0 -> bar 1, group 1 -> bar 2 (128 threads each)
#define GBAR(grp) asm volatile("bar.sync %0, 128;" :: "r"((grp) + 1) : "memory")

// 32-col B tile swizzle (2-term): [64 x 32] u32, conflict-free (R6-R16)
__device__ __forceinline__ int sidxB(int row, int col) {
    return row * 32 + (col ^ ((row & 7) * 4));
}
// 16-col tile swizzle (A tiles and hi-only B tiles), conflict-free (R11-R16)
__device__ __forceinline__ int sidxA(int row, int col) {
    return row * 16 + (col ^ (((row >> 1) & 3) * 4));
}

// ---------------------------------------------------------------------------
// Weight pre-transform (2-term): per chunk build 64x32 u32 tile:
// cols 0-15 = fp16 hi plane, 16-31 = fp16 lo plane, swizzled.
// ---------------------------------------------------------------------------
__global__ void transpose_W(const float* __restrict__ W, uint32_t* __restrict__ Bimg,
                            int total)
{
    const int e = blockIdx.x * 256 + threadIdx.x;
    if (e >= total) return;
    const int chunk = e >> 10;
    const int kp    = (e >> 6) & 15;
    const int n     = e & 63;
    const int kbase = chunk * 32 + kp * 2;
    const float w0 = W[(size_t)kbase * 64 + n];
    const float w1 = W[(size_t)(kbase + 1) * 64 + n];
    const float h0 = __half2float(__float2half_rn(w0));
    const float h1 = __half2float(__float2half_rn(w1));
    uint32_t* dst = Bimg + (size_t)chunk * 2048;
    dst[sidxB(n, kp)]      = packh(w0, w1);
    dst[sidxB(n, 16 + kp)] = packh(w0 - h0, w1 - h1);
}

// Hi-only variant: per chunk 64x16 u32 tile (sidxA swizzle), 4 KB/chunk.
__global__ void transpose_W16(const float* __restrict__ W, uint32_t* __restrict__ Bimg,
                              int total)
{
    const int e = blockIdx.x * 256 + threadIdx.x;
    if (e >= total) return;
    const int chunk = e >> 10;
    const int r     = e & 1023;
    const int n     = r >> 4;
    const int kp    = r & 15;
    const int kbase = chunk * 32 + kp * 2;
    const float w0 = W[(size_t)kbase * 64 + n];
    const float w1 = W[(size_t)(kbase + 1) * 64 + n];
    Bimg[(size_t)chunk * 1024 + sidxA(n, kp)] = packh(w0, w1);
}

// ---------------------------------------------------------------------------
// Feature pre-convert: fp32 [N, C] (+ optional BN affine) -> packed fp16.
// ---------------------------------------------------------------------------
__global__ __launch_bounds__(256)
void split_feats(const float* __restrict__ in, const float* __restrict__ ab,
                 uint32_t* __restrict__ outp, int N, int C)
{
    const int i = blockIdx.x * 256 + threadIdx.x;
    if (i >= N * (C / 4)) return;
    const int p = i / (C / 4);
    const int q = i - p * (C / 4);
    float4 v = ((const float4*)in)[i];
    if (ab) {
        const int ch = q * 4;
        v.x = v.x * ab[ch + 0] + ab[64 + ch + 0];
        v.y = v.y * ab[ch + 1] + ab[64 + ch + 1];
        v.z = v.z * ab[ch + 2] + ab[64 + ch + 2];
        v.w = v.w * ab[ch + 3] + ab[64 + ch + 3];
    }
    uint32_t* base = outp + (size_t)p * (C / 2);
    *(uint2*)&base[q * 2] = make_uint2(packh(v.x, v.y), packh(v.z, v.w));
}

// ---------------------------------------------------------------------------
// fp16 gather-GEMM conv. TERMS=2: A*Bh + A*Bl (split weights, exact).
// TERMS=1: A*Bh only (plain fp16 weights; used on the up conv, error-budgeted).
// Tile: 128 points x 64 Cout; TWO independent 4-warp pipelines with own
// buffers + named barriers; depth-3 rings; issue(c+2) 2 chunks ahead
// (R15 geometry, best measured).
// MODE 0: out = lrelu(acc), fp32 store + per-block BN stats partials
// MODE 1: u = acc + skip, stored directly as packed fp16
// ---------------------------------------------------------------------------
template<int KK, int CIN, int MODE, int TERMS>
__global__ __launch_bounds__(256)
void conv_mma(const uint32_t* __restrict__ feats,   // fp16 features [N, CIN/2] u32
              const uint32_t* __restrict__ Bimg,
              const int*   __restrict__ nbr,
              const float* __restrict__ skip,
              float*       __restrict__ out,
              uint32_t*    __restrict__ sout,
              float*       __restrict__ partials,
              int Nsrc, int Nout)
{
    constexpr int NSUB  = CIN / 32;
    constexpr int NCH   = KK * NSUB;
    constexpr int BTILE = TERMS * 1024;     // u32 per B chunk tile

    extern __shared__ uint32_t smu[];
    const uint32_t sb = smem_u32(smu);

    const int tid    = threadIdx.x;
    const int lane   = tid & 31;
    const int grp    = tid >> 7;            // pipeline group 0/1
    const int wg_tid = tid & 127;
    const int wwid   = (tid >> 5) & 3;      // warp within group
    const int g      = lane >> 2, t4 = lane & 3;
    const int wm     = wwid & 1,  wn = wwid >> 1;   // 2x2 warp grid per group
    const int n0     = blockIdx.x * 128;
    const int rbase  = grp * 64;            // group's row base within tile

    // SMEM bases (u32 units) for this group (depth-3 rings)
    const int A0 = grp * 3072;                      // 3 bufs x 1024
    const int B0 = 6144 + grp * 3 * BTILE;          // 3 bufs x BTILE

    float acc[2][4][4];
    #pragma unroll
    for (int mm = 0; mm < 2; ++mm)
        #pragma unroll
        for (int nn = 0; nn < 4; ++nn)
            #pragma unroll
            for (int q = 0; q < 4; ++q) acc[mm][nn][q] = 0.f;

    // Gather mapping: each thread owns 2 rows of its group's 64-row tile
    const int sub  = wg_tid & 3;            // 16B piece within 64B row-slice
    const int row0 = wg_tid >> 2;           // 0..31; rows row0, row0+32
    const int soffb = sub * 4;
    int cidx0 = Nsrc, cidx1 = Nsrc;

    auto issue = [&](int c, int buf) {
        const int k = c / NSUB, s = c - k * NSUB;
        const uint32_t Ab = sb + (A0 + buf * 1024) * 4;
        const uint32_t Bb = sb + (B0 + buf * BTILE) * 4;
        if (s == 0) {                       // refresh idx cache once per tap
            const int g0 = n0 + rbase + row0, g1 = n0 + rbase + row0 + 32;
            cidx0 = (g0 < Nout) ? nbr[(size_t)k * Nout + g0] : Nsrc;
            cidx1 = (g1 < Nout) ? nbr[(size_t)k * Nout + g1] : Nsrc;
        }
        {
            const bool v0 = (unsigned)cidx0 < (unsigned)Nsrc;
            const uint32_t* sp = feats + (size_t)(v0 ? cidx0 : 0) * (CIN / 2) + s * 16 + soffb;
            CP16(Ab + sidxA(row0, soffb) * 4, sp, v0 ? 16 : 0);
        }
        {
            const bool v1 = (unsigned)cidx1 < (unsigned)Nsrc;
            const uint32_t* sp = feats + (size_t)(v1 ? cidx1 : 0) * (CIN / 2) + s * 16 + soffb;
            CP16(Ab + sidxA(row0 + 32, soffb) * 4, sp, v1 ? 16 : 0);
        }
        const uint32_t* bs = Bimg + (size_t)c * BTILE;
        #pragma unroll
        for (int j = 0; j < TERMS * 2; ++j)
            CP16(Bb + (wg_tid + j * 128) * 16, bs + (wg_tid + j * 128) * 4, 16);
        CP_COMMIT();
    };

    auto compute = [&](int buf) {
        const uint32_t Ab = sb + (A0 + buf * 1024) * 4;
        const uint32_t Bb = sb + (B0 + buf * BTILE) * 4;
        #pragma unroll
        for (int ks = 0; ks < 2; ++ks) {
            uint32_t ah[2][4];
            #pragma unroll
            for (int mm = 0; mm < 2; ++mm) {
                const int arow = wm * 32 + mm * 16 + (lane & 15);
                const int acol = ks * 8 + (lane >> 4) * 4;
                LDSM4(ah[mm][0], ah[mm][1], ah[mm][2], ah[mm][3],
                      Ab + sidxA(arow, acol) * 4);
            }
            #pragma unroll
            for (int p = 0; p < 2; ++p) {
                uint32_t bh[4], bl[4];
                const int brow = wn * 32 + p * 16 + ((lane >> 4) & 1) * 8 + (lane & 7);
                const int bcol = ks * 8 + ((lane >> 3) & 1) * 4;
                if (TERMS == 2) {
                    LDSM4(bh[0], bh[1], bh[2], bh[3], Bb + sidxB(brow, bcol) * 4);
                    LDSM4(bl[0], bl[1], bl[2], bl[3], Bb + sidxB(brow, bcol + 16) * 4);
                } else {
                    LDSM4(bh[0], bh[1], bh[2], bh[3], Bb + sidxA(brow, bcol) * 4);
                }
                #pragma unroll
                for (int mm = 0; mm < 2; ++mm)
                    #pragma unroll
                    for (int nq = 0; nq < 2; ++nq) {
                        const int nn = p * 2 + nq;
                        mma_f16(acc[mm][nn], ah[mm], &bh[nq * 2]);
                        if (TERMS == 2)
                            mma_f16(acc[mm][nn], ah[mm], &bl[nq * 2]);
                    }
            }
        }
    };

    issue(0, 0);
    issue(1, 1);
    #pragma unroll 1
    for (int c = 0; c < NCH; ++c) {
        if (c < NCH - 1) asm volatile("cp.async.wait_group 1;" ::: "memory");
        else             asm volatile("cp.async.wait_group 0;" ::: "memory");
        GBAR(grp);                             // group-local barrier only
        if (c + 2 < NCH) issue(c + 2, (c + 2) % 3);
        compute(c % 3);
    }

    if (MODE == 1) {
        // --- epilogue: u = acc + skip, write packed fp16 directly ---
        #pragma unroll
        for (int mm = 0; mm < 2; ++mm)
            #pragma unroll
            for (int half = 0; half < 2; ++half) {
                const int r = n0 + rbase + wm * 32 + mm * 16 + g + half * 8;
                if (r < Nout) {
                    uint32_t* base = sout + (size_t)r * 32;
                    #pragma unroll
                    for (int nn = 0; nn < 4; ++nn) {
                        const int col = wn * 32 + nn * 8 + t4 * 2;
                        const float2 s2 = *(const float2*)&skip[(size_t)r * 64 + col];
                        const float v0 = acc[mm][nn][half * 2 + 0] + s2.x;
                        const float v1 = acc[mm][nn][half * 2 + 1] + s2.y;
                        base[col / 2] = packh(v0, v1);
                    }
                }
            }
    } else {
        // --- epilogue: lrelu, fp32 store, per-block BN stats partials ---
        float sl[8], ql[8];
        #pragma unroll
        for (int j = 0; j < 8; ++j) { sl[j] = 0.f; ql[j] = 0.f; }
        #pragma unroll
        for (int mm = 0; mm < 2; ++mm)
            #pragma unroll
            for (int half = 0; half < 2; ++half) {
                const int r = n0 + rbase + wm * 32 + mm * 16 + g + half * 8;
                if (r < Nout) {
                    #pragma unroll
                    for (int nn = 0; nn < 4; ++nn) {
                        float v0 = acc[mm][nn][half * 2 + 0];
                        float v1 = acc[mm][nn][half * 2 + 1];
                        v0 = v0 >= 0.f ? v0 : SLOPE * v0;
                        v1 = v1 >= 0.f ? v1 : SLOPE * v1;
                        const int col = wn * 32 + nn * 8 + t4 * 2;
                        *(float2*)&out[(size_t)r * 64 + col] = make_float2(v0, v1);
                        sl[nn * 2 + 0] += v0; ql[nn * 2 + 0] += v0 * v0;
                        sl[nn * 2 + 1] += v1; ql[nn * 2 + 1] += v1 * v1;
                    }
                }
            }
        __syncthreads();                 // both groups done; reuse conv SMEM
        float* red = (float*)smu;        // [2][64][32]
        const int ctr = (grp * 2 + wm) * 8 + g;     // 0..31 per column
        #pragma unroll
        for (int nn = 0; nn < 4; ++nn)
            #pragma unroll
            for (int b = 0; b < 2; ++b) {
                const int col = wn * 32 + nn * 8 + t4 * 2 + b;
                red[col * 32 + ctr]        = sl[nn * 2 + b];
                red[2048 + col * 32 + ctr] = ql[nn * 2 + b];
            }
        __syncthreads();
        if (tid < 128) {
            const int col = tid & 63, stat = tid >> 6;
            const float* src = red + stat * 2048 + col * 32;
            float s = 0.f;
            #pragma unroll
            for (int j = 0; j < 32; ++j) s += src[j];
            partials[blockIdx.x * 128 + stat * 64 + col] = s;
        }
    }
}

// ---------------------------------------------------------------------------
// Parallel finalize: grid = 64 blocks (one per channel), 256 threads.
// Fixed-order tree reduction -> deterministic.
// ---------------------------------------------------------------------------
__global__ __launch_bounds__(256)
void finalize_stats(const float* __restrict__ partial, int nblk, float invN,
                    const float* __restrict__ gamma, const float* __restrict__ beta,
                    float* __restrict__ ab)
{
    __shared__ double sh[256];
    const int ch   = blockIdx.x;
    const int t    = threadIdx.x;
    const int half = t >> 7;           // 0: S, 1: SS
    const int tt   = t & 127;
    double s = 0.0;
    for (int b = tt; b < nblk; b += 128)
        s += (double)partial[b * 128 + half * 64 + ch];
    sh[t] = s;
    __syncthreads();
    #pragma unroll
    for (int off = 64; off >= 1; off >>= 1) {
        if (tt < off) sh[t] += sh[t + off];
        __syncthreads();
    }
    if (t == 0) {
        const double S  = sh[0];
        const double SS = sh[128];
        const float m   = (float)(S * (double)invN);
        const float var = (float)(SS * (double)invN) - m * m;
        const float inv = rsqrtf(var + BN_EPS);
        const float a   = gamma[ch] * inv;
        ab[ch]      = a;
        ab[64 + ch] = beta[ch] - m * a;
    }
}

__global__ __launch_bounds__(256)
void apply_affine(const float* __restrict__ t, const float* __restrict__ ab,
                  float* __restrict__ out, int total4)
{
    const int i = blockIdx.x * blockDim.x + threadIdx.x;
    if (i >= total4) return;
    float4 v = ((const float4*)t)[i];
    const int c = (i & 15) * 4;
    v.x = v.x * ab[c + 0] + ab[64 + c + 0];
    v.y = v.y * ab[c + 1] + ab[64 + c + 1];
    v.z = v.z * ab[c + 2] + ab[64 + c + 2];
    v.w = v.w * ab[c + 3] + ab[64 + c + 3];
    ((float4*)out)[i] = v;
}

// ---------------------------------------------------------------------------
extern "C" void kernel_launch(void* const* d_in, const int* in_sizes, int n_in,
                              void* d_out, int out_size)
{
    const float* x      = (const float*)d_in[0];
    const float* skip   = (const float*)d_in[1];
    const int*   nbr_t  = (const int*)d_in[2];
    const int*   nbr_up = (const int*)d_in[3];
    const int*   nbr1   = (const int*)d_in[4];
    const int*   nbr2   = (const int*)d_in[5];
    const int*   nbr3   = (const int*)d_in[6];
    const float* Wt     = (const float*)d_in[7];
    const float* Wu     = (const float*)d_in[8];
    const float* W1     = (const float*)d_in[9];
    const float* W2     = (const float*)d_in[10];
    const float* W3     = (const float*)d_in[11];
    const float* gt = (const float*)d_in[12]; const float* bt = (const float*)d_in[13];
    const float* g1 = (const float*)d_in[14]; const float* b1 = (const float*)d_in[15];
    const float* g2 = (const float*)d_in[16]; const float* b2 = (const float*)d_in[17];
    const float* g3 = (const float*)d_in[18]; const float* b3 = (const float*)d_in[19];

    const int N_in  = in_sizes[0] / 128;   // 80000
    const int N_out = in_sizes[1] / 64;    // 200000
    float* out = (float*)d_out;

    float *h_, *t1_, *t2_, *t3_, *part_, *ab_;
    uint32_t *bimg_, *s0_, *s1_;
    cudaGetSymbolAddress((void**)&h_,    g_h);
    cudaGetSymbolAddress((void**)&t1_,   g_t1);
    cudaGetSymbolAddress((void**)&t2_,   g_t2);
    cudaGetSymbolAddress((void**)&t3_,   g_t3);
    cudaGetSymbolAddress((void**)&part_, g_part);
    cudaGetSymbolAddress((void**)&ab_,   g_ab);
    cudaGetSymbolAddress((void**)&bimg_, g_Bimg);
    cudaGetSymbolAddress((void**)&s0_,   g_s0);
    cudaGetSymbolAddress((void**)&s1_,   g_s1);

    const int SMEM2 = (6144 + 6 * 2048) * 4;    // 73728 B (2-term convs)
    const int SMEM1 = (6144 + 6 * 1024) * 4;    // 49152 B (hi-only up conv)

    cudaFuncSetAttribute(conv_mma<27, 128, 0, 2>, cudaFuncAttributeMaxDynamicSharedMemorySize, SMEM2);
    cudaFuncSetAttribute(conv_mma<27,  64, 1, 1>, cudaFuncAttributeMaxDynamicSharedMemorySize, SMEM1);
    cudaFuncSetAttribute(conv_mma< 9,  64, 0, 2>, cudaFuncAttributeMaxDynamicSharedMemorySize, SMEM2);
    cudaFuncSetAttribute(conv_mma<27,  64, 0, 2>, cudaFuncAttributeMaxDynamicSharedMemorySize, SMEM2);

    const int gin  = (N_in  + 127) / 128;   // 625
    const int gout = (N_out + 127) / 128;   // 1563

    // [0] convert x -> fp16 s0
    split_feats<<<(N_in * 32 + 255) / 256, 256>>>(x, nullptr, s0_, N_in, 128);
    // [1][2] weight transposes needed before the first conv
    transpose_W  <<<(108 * 1024 + 255) / 256, 256>>>(Wt, bimg_ + BOFF_T, 108 * 1024);
    transpose_W16<<<( 54 * 1024 + 255) / 256, 256>>>(Wu, bimg_ + BOFF_U,  54 * 1024);
    // [3] trans conv (the slot ncu samples) + lrelu -> h + stats
    conv_mma<27, 128, 0, 2><<<gin, 256, SMEM2>>>(s0_, bimg_ + BOFF_T, nbr_t, nullptr, h_, nullptr, part_, N_in, N_in);
    // remaining weight transposes (off critical path)
    transpose_W<<<( 18 * 1024 + 255) / 256, 256>>>(W1, bimg_ + BOFF_1,  18 * 1024);
    transpose_W<<<( 18 * 1024 + 255) / 256, 256>>>(W2, bimg_ + BOFF_2,  18 * 1024);
    transpose_W<<<( 54 * 1024 + 255) / 256, 256>>>(W3, bimg_ + BOFF_3,  54 * 1024);
    // finalize ab0 ; convert h
    finalize_stats<<<64, 256>>>(part_, gin, 1.0f / N_in, gt, bt, ab_ + 0);
    split_feats<<<(N_in * 16 + 255) / 256, 256>>>(h_, ab_ + 0, s1_, N_in, 64);

    // inverse conv (hi-only weights) + skip -> fp16 u directly into s0
    conv_mma<27, 64, 1, 1><<<gout, 256, SMEM1>>>(s1_, bimg_ + BOFF_U, nbr_up, skip, nullptr, s0_, nullptr, N_in, N_out);

    // conv1 + lrelu -> t1 + stats ; finalize ab1 ; convert
    conv_mma<9, 64, 0, 2><<<gout, 256, SMEM2>>>(s0_, bimg_ + BOFF_1, nbr1, nullptr, t1_, nullptr, part_, N_out, N_out);
    finalize_stats<<<64, 256>>>(part_, gout, 1.0f / N_out, g1, b1, ab_ + 128);
    split_feats<<<(N_out * 16 + 255) / 256, 256>>>(t1_, ab_ + 128, s1_, N_out, 64);

    // conv2 + lrelu -> t2 + stats ; finalize ab2 ; convert
    conv_mma<9, 64, 0, 2><<<gout, 256, SMEM2>>>(s1_, bimg_ + BOFF_2, nbr2, nullptr, t2_, nullptr, part_, N_out, N_out);
    finalize_stats<<<64, 256>>>(part_, gout, 1.0f / N_out, g2, b2, ab_ + 256);
    split_feats<<<(N_out * 16 + 255) / 256, 256>>>(t2_, ab_ + 256, s0_, N_out, 64);

    // conv3 + lrelu -> t3 + stats ; finalize ab3
    conv_mma<27, 64, 0, 2><<<gout, 256, SMEM2>>>(s0_, bimg_ + BOFF_3, nbr3, nullptr, t3_, nullptr, part_, N_out, N_out);
    finalize_stats<<<64, 256>>>(part_, gout, 1.0f / N_out, g3, b3, ab_ + 384);

    // final BN3 apply -> d_out
    const int total4 = N_out * 16;
    apply_affine<<<(total4 + 255) / 256, 256>>>(t3_, ab_ + 384, out, total4);
}